// round 5
// baseline (speedup 1.0000x reference)
#include <cuda_runtime.h>

#define NN 100000
#define NE 800000
#define NG 512
#define IND 16
#define HID 64
#define MH  32
#define NL  3
#define EPSB 1e-5f
#define NTILE (NE/32)     // 25000 edge tiles of 32
#define NODE_TILES 1563   // ceil(NN/64)

#define GRID_P 1184       // 8 blocks per SM (148 SMs)

// ------------------- f32x2 packed helpers -------------------
__device__ __forceinline__ unsigned long long pk2(float lo, float hi) {
    unsigned long long r;
    asm("mov.b64 %0,{%1,%2};" : "=l"(r) : "f"(lo), "f"(hi));
    return r;
}
__device__ __forceinline__ void upk2(unsigned long long v, float& lo, float& hi) {
    asm("mov.b64 {%0,%1},%2;" : "=f"(lo), "=f"(hi) : "l"(v));
}
__device__ __forceinline__ unsigned long long f2fma(unsigned long long a,
                                                    unsigned long long b,
                                                    unsigned long long c) {
    unsigned long long r;
    asm("fma.rn.f32x2 %0,%1,%2,%3;" : "=l"(r) : "l"(a), "l"(b), "l"(c));
    return r;
}
__device__ __forceinline__ unsigned long long f2add(unsigned long long a,
                                                    unsigned long long b) {
    unsigned long long r;
    asm("add.rn.f32x2 %0,%1,%2;" : "=l"(r) : "l"(a), "l"(b));
    return r;
}

// ------------------- scratch (static device memory; no allocs) -------------------
__device__ float g_h[NN*HID];
__device__ float g_Pa[NN*MH];
__device__ float g_Pb[NN*MH];
__device__ float g_nsum[NN*HID];
__device__ float g_z3[NN*MH];
__device__ float g_y4[NN*HID];
__device__ float g_deg[NN];
__device__ float g_statsAll[12*128];  // per (layer,stage): [0..63] sum, [64..127] sumsq
__device__ float g_pool[NG*HID];
__device__ float g_pcnt[NG];

// ------------------- prep -------------------
__global__ void k_prep() {
    int i = blockIdx.x*blockDim.x + threadIdx.x;
    if (i < NN)       g_deg[i]  = 0.f;
    if (i < NG*HID)   g_pool[i] = 0.f;
    if (i < NG)       g_pcnt[i] = 0.f;
    if (i < 12*128)   g_statsAll[i] = 0.f;
}

__global__ void k_deg(const int* __restrict__ ei) {
    int e = blockIdx.x*blockDim.x + threadIdx.x;
    if (e < NE) atomicAdd(&g_deg[ei[NE + e]], 1.0f);
}

// ------------------- input projection: h = x @ Win + b -------------------
__global__ __launch_bounds__(256) void k_init(const float* __restrict__ x,
                                              const float* __restrict__ w,
                                              const float* __restrict__ b) {
    __shared__ float Ws[IND*HID];
    __shared__ float bs[HID];
    __shared__ float xs[4][IND];
    int t = threadIdx.x;
    for (int i = t; i < IND*HID; i += 256) Ws[i] = w[i];
    if (t < HID) bs[t] = b[t];
    int ni = t >> 6, c = t & 63;
    for (int node0 = blockIdx.x*4; node0 < NN; node0 += gridDim.x*4) {
        if (t < 4*IND) xs[t/IND][t%IND] = x[(node0 + t/IND)*IND + (t%IND)];
        __syncthreads();
        int n = node0 + ni;
        float acc = bs[c];
        #pragma unroll
        for (int k = 0; k < IND; k++) acc = fmaf(xs[ni][k], Ws[k*HID + c], acc);
        g_h[n*HID + c] = acc;
        __syncthreads();
    }
}

// ------------------- nodeA: fold residual(BN4), zero nsum, Pa/Pb = h @ [W1a|W1b] -------
// register-tiled 64x64 GEMM, one 64-node tile per block
__global__ __launch_bounds__(256) void k_nodeA(const float* __restrict__ msg_w1,
                                               const float* __restrict__ g2,
                                               const float* __restrict__ be2,
                                               int l) {
    __shared__ float Hs[64][66];
    __shared__ unsigned long long Wp[32][64];   // 16KB
    __shared__ float a4s[64], c4s[64];
    int t = threadIdx.x;
    int fold = (l > 0);
    if (t < 64) {
        float a = 0.f, c = 0.f;
        if (fold) {
            const float* st = g_statsAll + (4*(l-1)+3)*128;
            float mu  = st[t] * (1.0f/NN);
            float var = st[64+t] * (1.0f/NN) - mu*mu;
            a = g2[(l-1)*HID + t] * rsqrtf(var + EPSB);
            c = be2[(l-1)*HID + t] - a*mu;
        }
        a4s[t] = a; c4s[t] = c;
    }
    const float* W = msg_w1 + l*129*MH;
    for (int i = t; i < 32*64; i += 256) {
        int kp = i >> 6, c = i & 63;
        float w0, w1;
        if (c < 32) { w0 = W[(2*kp)*MH + c];          w1 = W[(2*kp+1)*MH + c]; }
        else        { w0 = W[(64+2*kp)*MH + (c-32)];  w1 = W[(64+2*kp+1)*MH + (c-32)]; }
        Wp[kp][c] = pk2(w0, w1);
    }
    __syncthreads();
    int n0 = blockIdx.x * 64;
    {
        int row = t >> 2, cb = (t & 3) * 16;
        int n = n0 + row;
        if (n < NN) {
            float4 z4 = make_float4(0.f,0.f,0.f,0.f);
            #pragma unroll
            for (int u = 0; u < 4; u++) {
                int c = cb + 4*u;
                float4 v = *reinterpret_cast<const float4*>(g_h + n*HID + c);
                if (fold) {
                    float4 y = *reinterpret_cast<const float4*>(g_y4 + n*HID + c);
                    v.x = fmaf(a4s[c+0], y.x, v.x) + c4s[c+0];
                    v.y = fmaf(a4s[c+1], y.y, v.y) + c4s[c+1];
                    v.z = fmaf(a4s[c+2], y.z, v.z) + c4s[c+2];
                    v.w = fmaf(a4s[c+3], y.w, v.w) + c4s[c+3];
                    *reinterpret_cast<float4*>(g_h + n*HID + c) = v;
                }
                *reinterpret_cast<float4*>(g_nsum + n*HID + c) = z4;
                Hs[row][c+0] = v.x; Hs[row][c+1] = v.y;
                Hs[row][c+2] = v.z; Hs[row][c+3] = v.w;
            }
        } else {
            #pragma unroll
            for (int u = 0; u < 16; u++) Hs[row][cb+u] = 0.f;
        }
    }
    __syncthreads();
    int r = t >> 4, q = t & 15;
    unsigned long long acc[4][4];
    #pragma unroll
    for (int n = 0; n < 4; n++)
        #pragma unroll
        for (int c = 0; c < 4; c++) acc[n][c] = 0ULL;
    #pragma unroll 4
    for (int kp = 0; kp < 32; kp++) {
        unsigned long long h2[4];
        #pragma unroll
        for (int n = 0; n < 4; n++)
            h2[n] = *reinterpret_cast<const unsigned long long*>(&Hs[4*r+n][2*kp]);
        ulonglong2 wA = *reinterpret_cast<const ulonglong2*>(&Wp[kp][4*q]);
        ulonglong2 wB = *reinterpret_cast<const ulonglong2*>(&Wp[kp][4*q+2]);
        #pragma unroll
        for (int n = 0; n < 4; n++) {
            acc[n][0] = f2fma(h2[n], wA.x, acc[n][0]);
            acc[n][1] = f2fma(h2[n], wA.y, acc[n][1]);
            acc[n][2] = f2fma(h2[n], wB.x, acc[n][2]);
            acc[n][3] = f2fma(h2[n], wB.y, acc[n][3]);
        }
    }
    #pragma unroll
    for (int n = 0; n < 4; n++) {
        int node = n0 + 4*r + n;
        if (node < NN) {
            float4 o; float lo, hi;
            upk2(acc[n][0], lo, hi); o.x = lo + hi;
            upk2(acc[n][1], lo, hi); o.y = lo + hi;
            upk2(acc[n][2], lo, hi); o.z = lo + hi;
            upk2(acc[n][3], lo, hi); o.w = lo + hi;
            if (q < 8) *reinterpret_cast<float4*>(g_Pa + node*MH + 4*q)        = o;
            else       *reinterpret_cast<float4*>(g_Pb + node*MH + 4*q - 32)   = o;
        }
    }
}

// ------------------- edge stats: register-accumulated Σ z1, Σ z1² -------------------
__global__ __launch_bounds__(256) void k_edge_stats(const int* __restrict__ ei,
                                                    const float* __restrict__ eattr,
                                                    const float* __restrict__ msg_w1,
                                                    const float* __restrict__ msg_b1,
                                                    int l) {
    __shared__ unsigned long long wcp[16], b1p[16];
    __shared__ float sh[128];
    int t = threadIdx.x;
    if (t < 16) {
        const float* wc = msg_w1 + l*129*MH + 128*MH;
        const float* b1 = msg_b1 + l*MH;
        wcp[t] = pk2(wc[2*t], wc[2*t+1]);
        b1p[t] = pk2(b1[2*t], b1[2*t+1]);
    }
    if (t < 128) sh[t] = 0.f;
    __syncthreads();
    unsigned long long sS[16], sQ[16];
    #pragma unroll
    for (int k = 0; k < 16; k++) { sS[k] = 0ULL; sQ[k] = 0ULL; }
    int stride = gridDim.x*blockDim.x;
    for (int e = blockIdx.x*blockDim.x + t; e < NE; e += stride) {
        int s = ei[e], d = ei[NE + e];
        float ea = eattr[e];
        unsigned long long ea2 = pk2(ea, ea);
        const float4* pa = reinterpret_cast<const float4*>(g_Pa + d*MH);
        const float4* pb = reinterpret_cast<const float4*>(g_Pb + s*MH);
        #pragma unroll
        for (int i = 0; i < 8; i++) {
            float4 A = pa[i], B = pb[i];
            unsigned long long a01 = pk2(A.x, A.y), a23 = pk2(A.z, A.w);
            unsigned long long b01 = pk2(B.x, B.y), b23 = pk2(B.z, B.w);
            unsigned long long z0 = f2add(f2add(a01, b01), f2fma(ea2, wcp[2*i],   b1p[2*i]));
            unsigned long long z1 = f2add(f2add(a23, b23), f2fma(ea2, wcp[2*i+1], b1p[2*i+1]));
            sS[2*i]   = f2add(sS[2*i],   z0);
            sQ[2*i]   = f2fma(z0, z0, sQ[2*i]);
            sS[2*i+1] = f2add(sS[2*i+1], z1);
            sQ[2*i+1] = f2fma(z1, z1, sQ[2*i+1]);
        }
    }
    #pragma unroll
    for (int k = 0; k < 16; k++) {
        float lo, hi;
        upk2(sS[k], lo, hi);
        atomicAdd(&sh[2*k], lo);      atomicAdd(&sh[2*k+1], hi);
        upk2(sQ[k], lo, hi);
        atomicAdd(&sh[64+2*k], lo);   atomicAdd(&sh[64+2*k+1], hi);
    }
    __syncthreads();
    if (t < 128) atomicAdd(&g_statsAll[(4*l)*128 + t], sh[t]);
}

// ------------------- edge main: BN1(fold)+ReLU, @W2, ReLU, scatter, stats -------------
__global__ __launch_bounds__(256) void k_edge_main(const int* __restrict__ ei,
                                                   const float* __restrict__ eattr,
                                                   const float* __restrict__ msg_w1,
                                                   const float* __restrict__ msg_b1,
                                                   const float* __restrict__ msg_w2,
                                                   const float* __restrict__ msg_b2,
                                                   const float* __restrict__ g1,
                                                   const float* __restrict__ be1,
                                                   int l) {
    __shared__ float m_s[8][32*34];
    __shared__ int   d_s[8][32];
    __shared__ float a1s[MH], wps[MH], bps[MH];
    __shared__ float sh[128];
    int t = threadIdx.x, wq = t >> 5, lane = t & 31;
    const float* W2 = msg_w2 + l*MH*HID;
    if (t < MH) {
        const float* st = g_statsAll + (4*l)*128;
        float mu  = st[t] * (1.0f/NE);
        float var = st[64+t] * (1.0f/NE) - mu*mu;
        float a1 = g1[l*MH + t] * rsqrtf(var + EPSB);
        float c1 = be1[l*MH + t] - a1*mu;
        a1s[t] = a1;
        wps[t] = a1 * msg_w1[l*129*MH + 128*MH + t];
        bps[t] = fmaf(a1, msg_b1[l*MH + t], c1);
    }
    if (t < 128) sh[t] = 0.f;
    unsigned long long WA[16], WB[16];
    #pragma unroll
    for (int kk = 0; kk < 16; kk++) {
        WA[kk] = pk2(W2[(2*kk)*HID + lane],      W2[(2*kk+1)*HID + lane]);
        WB[kk] = pk2(W2[(2*kk)*HID + lane + 32], W2[(2*kk+1)*HID + lane + 32]);
    }
    float b2a = msg_b2[l*HID + lane], b2b = msg_b2[l*HID + lane + 32];
    __syncthreads();
    float sS0 = 0.f, sQ0 = 0.f, sS1 = 0.f, sQ1 = 0.f;
    for (int tile = blockIdx.x*8 + wq; tile < NTILE; tile += gridDim.x*8) {
        int e = tile*32 + lane;
        int s = ei[e], d = ei[NE + e];
        float ea = eattr[e];
        d_s[wq][lane] = d;
        const float4* pa = reinterpret_cast<const float4*>(g_Pa + d*MH);
        const float4* pb = reinterpret_cast<const float4*>(g_Pb + s*MH);
        float* mr = &m_s[wq][lane*34];
        #pragma unroll
        for (int i = 0; i < 8; i++) {
            float4 A = pa[i], B = pb[i]; int c0 = 4*i;
            mr[c0+0] = fmaxf(fmaf(a1s[c0+0], A.x + B.x, fmaf(ea, wps[c0+0], bps[c0+0])), 0.f);
            mr[c0+1] = fmaxf(fmaf(a1s[c0+1], A.y + B.y, fmaf(ea, wps[c0+1], bps[c0+1])), 0.f);
            mr[c0+2] = fmaxf(fmaf(a1s[c0+2], A.z + B.z, fmaf(ea, wps[c0+2], bps[c0+2])), 0.f);
            mr[c0+3] = fmaxf(fmaf(a1s[c0+3], A.w + B.w, fmaf(ea, wps[c0+3], bps[c0+3])), 0.f);
        }
        __syncwarp();
        #pragma unroll 2
        for (int e2 = 0; e2 < 32; e2++) {
            const unsigned long long* mp =
                reinterpret_cast<const unsigned long long*>(&m_s[wq][e2*34]);
            unsigned long long accA = 0ULL, accB = 0ULL;
            #pragma unroll
            for (int kk = 0; kk < 16; kk++) {
                unsigned long long m2 = mp[kk];
                accA = f2fma(m2, WA[kk], accA);
                accB = f2fma(m2, WB[kk], accB);
            }
            float a0, a1v, b0, b1v;
            upk2(accA, a0, a1v); upk2(accB, b0, b1v);
            float y0 = fmaxf(a0 + a1v + b2a, 0.f);
            float y1 = fmaxf(b0 + b1v + b2b, 0.f);
            sS0 += y0; sQ0 = fmaf(y0, y0, sQ0);
            sS1 += y1; sQ1 = fmaf(y1, y1, sQ1);
            int dd = d_s[wq][e2];
            atomicAdd(&g_nsum[dd*HID + lane],      y0);
            atomicAdd(&g_nsum[dd*HID + lane + 32], y1);
        }
        __syncwarp();
    }
    atomicAdd(&sh[lane],      sS0);
    atomicAdd(&sh[64 + lane], sQ0);
    atomicAdd(&sh[32 + lane], sS1);
    atomicAdd(&sh[96 + lane], sQ1);
    __syncthreads();
    if (t < 128) atomicAdd(&g_statsAll[(4*l+1)*128 + t], sh[t]);
}

// ------------------- update1: z3 = [h, BN2(nsum,deg)] @ U1 + b, stats ---------------
// register-tiled, K split in two halves of 64 (32 k-pairs each)
__global__ __launch_bounds__(256) void k_update1(const float* __restrict__ upd_w1,
                                                 const float* __restrict__ upd_b1,
                                                 const float* __restrict__ g2m,
                                                 const float* __restrict__ be2m,
                                                 int l) {
    __shared__ float Rs[64][66];                 // 16.9KB (one K half)
    __shared__ unsigned long long Wp1[64][32];   // 16KB
    __shared__ float a2s[64], c2s[64];
    __shared__ float sh[128];
    int t = threadIdx.x;
    if (t < 64) {
        const float* st = g_statsAll + (4*l+1)*128;
        float mu  = st[t] * (1.0f/NE);
        float var = st[64+t] * (1.0f/NE) - mu*mu;
        float a = g2m[l*HID + t] * rsqrtf(var + EPSB);
        a2s[t] = a; c2s[t] = be2m[l*HID + t] - a*mu;
    }
    if (t < 128) sh[t] = 0.f;
    const float* U1 = upd_w1 + l*128*MH;
    for (int i = t; i < 64*32; i += 256) {
        int kp = i >> 5, j = i & 31;
        Wp1[kp][j] = pk2(U1[(2*kp)*MH + j], U1[(2*kp+1)*MH + j]);
    }
    int n0 = blockIdx.x * 64;
    int row = t >> 2, cb = (t & 3) * 16;
    int nrow = n0 + row;
    int r = t >> 4, q = t & 15;
    unsigned long long acc[4][2];
    #pragma unroll
    for (int n = 0; n < 4; n++) { acc[n][0] = 0ULL; acc[n][1] = 0ULL; }

    // ---- half 1: k = 0..63 (h part) ----
    __syncthreads();
    if (nrow < NN) {
        #pragma unroll
        for (int u = 0; u < 4; u++) {
            int c = cb + 4*u;
            float4 v = *reinterpret_cast<const float4*>(g_h + nrow*HID + c);
            Rs[row][c+0] = v.x; Rs[row][c+1] = v.y; Rs[row][c+2] = v.z; Rs[row][c+3] = v.w;
        }
    } else {
        #pragma unroll
        for (int u = 0; u < 16; u++) Rs[row][cb+u] = 0.f;
    }
    __syncthreads();
    #pragma unroll 4
    for (int kp = 0; kp < 32; kp++) {
        unsigned long long h2[4];
        #pragma unroll
        for (int n = 0; n < 4; n++)
            h2[n] = *reinterpret_cast<const unsigned long long*>(&Rs[4*r+n][2*kp]);
        ulonglong2 w = *reinterpret_cast<const ulonglong2*>(&Wp1[kp][2*q]);
        #pragma unroll
        for (int n = 0; n < 4; n++) {
            acc[n][0] = f2fma(h2[n], w.x, acc[n][0]);
            acc[n][1] = f2fma(h2[n], w.y, acc[n][1]);
        }
    }
    // ---- half 2: k = 64..127 (agg part) ----
    __syncthreads();
    if (nrow < NN) {
        float dg = g_deg[nrow];
        #pragma unroll
        for (int u = 0; u < 4; u++) {
            int c = cb + 4*u;
            float4 v = *reinterpret_cast<const float4*>(g_nsum + nrow*HID + c);
            v.x = fmaf(a2s[c+0], v.x, c2s[c+0]*dg);
            v.y = fmaf(a2s[c+1], v.y, c2s[c+1]*dg);
            v.z = fmaf(a2s[c+2], v.z, c2s[c+2]*dg);
            v.w = fmaf(a2s[c+3], v.w, c2s[c+3]*dg);
            Rs[row][c+0] = v.x; Rs[row][c+1] = v.y; Rs[row][c+2] = v.z; Rs[row][c+3] = v.w;
        }
    } else {
        #pragma unroll
        for (int u = 0; u < 16; u++) Rs[row][cb+u] = 0.f;
    }
    __syncthreads();
    #pragma unroll 4
    for (int kp = 0; kp < 32; kp++) {
        unsigned long long h2[4];
        #pragma unroll
        for (int n = 0; n < 4; n++)
            h2[n] = *reinterpret_cast<const unsigned long long*>(&Rs[4*r+n][2*kp]);
        ulonglong2 w = *reinterpret_cast<const ulonglong2*>(&Wp1[32+kp][2*q]);
        #pragma unroll
        for (int n = 0; n < 4; n++) {
            acc[n][0] = f2fma(h2[n], w.x, acc[n][0]);
            acc[n][1] = f2fma(h2[n], w.y, acc[n][1]);
        }
    }
    // ---- epilogue ----
    float b30 = upd_b1[l*MH + 2*q], b31 = upd_b1[l*MH + 2*q + 1];
    float s0 = 0.f, q0 = 0.f, s1 = 0.f, q1 = 0.f;
    #pragma unroll
    for (int n = 0; n < 4; n++) {
        int node = n0 + 4*r + n;
        if (node < NN) {
            float lo, hi;
            upk2(acc[n][0], lo, hi); float z0 = lo + hi + b30;
            upk2(acc[n][1], lo, hi); float z1 = lo + hi + b31;
            *reinterpret_cast<float2*>(g_z3 + node*MH + 2*q) = make_float2(z0, z1);
            s0 += z0; q0 = fmaf(z0, z0, q0);
            s1 += z1; q1 = fmaf(z1, z1, q1);
        }
    }
    atomicAdd(&sh[2*q],      s0);
    atomicAdd(&sh[2*q+1],    s1);
    atomicAdd(&sh[64+2*q],   q0);
    atomicAdd(&sh[64+2*q+1], q1);
    __syncthreads();
    if (t < 128) atomicAdd(&g_statsAll[(4*l+2)*128 + t], sh[t]);
}

// ------------------- update2: m3 = relu(BN3(z3)), y4 = relu(m3@U2+b), stats ----------
__global__ __launch_bounds__(256) void k_update2(const float* __restrict__ upd_w2,
                                                 const float* __restrict__ upd_b2,
                                                 const float* __restrict__ g1u,
                                                 const float* __restrict__ be1u,
                                                 int l) {
    __shared__ float m3s[4*MH];
    __shared__ float a3s[MH], c3s[MH];
    __shared__ float sh[128];
    int t = threadIdx.x, ni = t >> 6, c = t & 63;
    const float* U2 = upd_w2 + l*MH*HID;
    unsigned long long Up[16];
    #pragma unroll
    for (int kk = 0; kk < 16; kk++)
        Up[kk] = pk2(U2[(2*kk)*HID + c], U2[(2*kk+1)*HID + c]);
    if (t < MH) {
        const float* st = g_statsAll + (4*l+2)*128;
        float mu  = st[t] * (1.0f/NN);
        float var = st[64+t] * (1.0f/NN) - mu*mu;
        float a = g1u[l*MH + t] * rsqrtf(var + EPSB);
        a3s[t] = a; c3s[t] = be1u[l*MH + t] - a*mu;
    }
    if (t < 128) sh[t] = 0.f;
    float b4 = upd_b2[l*HID + c];
    __syncthreads();
    float accS = 0.f, accQ = 0.f;
    for (int node0 = blockIdx.x*4; node0 < NN; node0 += gridDim.x*4) {
        if (t < 4*MH) {
            int ni2 = t >> 5, k = t & 31;
            float z = g_z3[(node0 + ni2)*MH + k];
            m3s[t] = fmaxf(fmaf(a3s[k], z, c3s[k]), 0.f);
        }
        __syncthreads();
        int n = node0 + ni;
        const unsigned long long* mp =
            reinterpret_cast<const unsigned long long*>(m3s + ni*MH);
        unsigned long long acc = 0ULL;
        #pragma unroll
        for (int kk = 0; kk < 16; kk++) acc = f2fma(mp[kk], Up[kk], acc);
        float lo, hi; upk2(acc, lo, hi);
        float y = fmaxf(lo + hi + b4, 0.f);
        g_y4[n*HID + c] = y;
        accS += y; accQ = fmaf(y, y, accQ);
        __syncthreads();
    }
    atomicAdd(&sh[c], accS);
    atomicAdd(&sh[64 + c], accQ);
    __syncthreads();
    if (t < 128) atomicAdd(&g_statsAll[(4*l+3)*128 + t], sh[t]);
}

// ------------------- pooling (folds last residual, BN4 consts in prologue) ----------
__global__ __launch_bounds__(256) void k_pool(const int* __restrict__ batch,
                                              const float* __restrict__ g2,
                                              const float* __restrict__ be2) {
    __shared__ float a4s[64], c4s[64];
    int t = threadIdx.x;
    if (t < 64) {
        const float* st = g_statsAll + 11*128;
        float mu  = st[t] * (1.0f/NN);
        float var = st[64+t] * (1.0f/NN) - mu*mu;
        float a = g2[2*HID + t] * rsqrtf(var + EPSB);
        a4s[t] = a; c4s[t] = be2[2*HID + t] - a*mu;
    }
    __syncthreads();
    int node0 = blockIdx.x*4;
    int ni = t >> 6, c = t & 63;
    int n = node0 + ni;
    if (n >= NN) return;
    float hn = fmaf(a4s[c], g_y4[n*HID + c], g_h[n*HID + c]) + c4s[c];
    int b = batch[n];
    atomicAdd(&g_pool[b*HID + c], hn);
    if (c == 0) atomicAdd(&g_pcnt[b], 1.0f);
}

__global__ void k_head(const float* __restrict__ out_w, const float* __restrict__ out_b,
                       float* __restrict__ out) {
    int g = blockIdx.x*blockDim.x + threadIdx.x;
    if (g >= NG) return;
    float acc = 0.f;
    #pragma unroll
    for (int k = 0; k < HID; k++) acc = fmaf(g_pool[g*HID + k], __ldg(&out_w[k]), acc);
    float cnt = fmaxf(g_pcnt[g], 1.0f);
    out[g] = fmaxf(acc / cnt + __ldg(&out_b[0]), 0.f);
}

// ------------------- launcher -------------------
extern "C" void kernel_launch(void* const* d_in, const int* in_sizes, int n_in,
                              void* d_out, int out_size) {
    const float* x        = (const float*)d_in[0];
    const int*   ei       = (const int*)  d_in[1];
    const float* eattr    = (const float*)d_in[2];
    const int*   batch    = (const int*)  d_in[3];
    const float* lin_in_w = (const float*)d_in[4];
    const float* lin_in_b = (const float*)d_in[5];
    const float* msg_w1   = (const float*)d_in[6];
    const float* msg_b1   = (const float*)d_in[7];
    const float* msg_g1   = (const float*)d_in[8];
    const float* msg_be1  = (const float*)d_in[9];
    const float* msg_w2   = (const float*)d_in[10];
    const float* msg_b2   = (const float*)d_in[11];
    const float* msg_g2   = (const float*)d_in[12];
    const float* msg_be2  = (const float*)d_in[13];
    const float* upd_w1   = (const float*)d_in[14];
    const float* upd_b1   = (const float*)d_in[15];
    const float* upd_g1   = (const float*)d_in[16];
    const float* upd_be1  = (const float*)d_in[17];
    const float* upd_w2   = (const float*)d_in[18];
    const float* upd_b2   = (const float*)d_in[19];
    const float* upd_g2   = (const float*)d_in[20];
    const float* upd_be2  = (const float*)d_in[21];
    const float* out_w    = (const float*)d_in[22];
    const float* out_b    = (const float*)d_in[23];
    float* out = (float*)d_out;

    k_prep<<<(NN + 255)/256, 256>>>();
    k_deg<<<NE/256, 256>>>(ei);
    k_init<<<GRID_P, 256>>>(x, lin_in_w, lin_in_b);

    for (int l = 0; l < NL; l++) {
        k_nodeA<<<NODE_TILES, 256>>>(msg_w1, upd_g2, upd_be2, l);
        k_edge_stats<<<GRID_P, 256>>>(ei, eattr, msg_w1, msg_b1, l);
        k_edge_main<<<GRID_P, 256>>>(ei, eattr, msg_w1, msg_b1, msg_w2, msg_b2,
                                     msg_g1, msg_be1, l);
        k_update1<<<NODE_TILES, 256>>>(upd_w1, upd_b1, msg_g2, msg_be2, l);
        k_update2<<<GRID_P, 256>>>(upd_w2, upd_b2, upd_g1, upd_be1, l);
    }

    k_pool<<<NN/4, 256>>>(batch, upd_g2, upd_be2);
    k_head<<<2, 256>>>(out_w, out_b, out);
}

// round 8
// speedup vs baseline: 3.3662x; 3.3662x over previous
#include <cuda_runtime.h>

#define NN 100000
#define NE 800000
#define NG 512
#define IND 16
#define HID 64
#define MH  32
#define NL  3
#define EPSB 1e-5f
#define NTILE (NE/32)     // 25000 edge tiles of 32
#define NODE_TILES 1563   // ceil(NN/64)

#define GRID_P 1184       // 8 blocks per SM (148 SMs)

// ------------------- f32x2 packed helpers -------------------
__device__ __forceinline__ unsigned long long pk2(float lo, float hi) {
    unsigned long long r;
    asm("mov.b64 %0,{%1,%2};" : "=l"(r) : "f"(lo), "f"(hi));
    return r;
}
__device__ __forceinline__ void upk2(unsigned long long v, float& lo, float& hi) {
    asm("mov.b64 {%0,%1},%2;" : "=f"(lo), "=f"(hi) : "l"(v));
}
__device__ __forceinline__ unsigned long long f2fma(unsigned long long a,
                                                    unsigned long long b,
                                                    unsigned long long c) {
    unsigned long long r;
    asm("fma.rn.f32x2 %0,%1,%2,%3;" : "=l"(r) : "l"(a), "l"(b), "l"(c));
    return r;
}

// ------------------- scratch (static device memory; no allocs) -------------------
__device__ float g_h[NN*HID];
__device__ float g_Pa[NN*MH];
__device__ float g_Pb[NN*MH];
__device__ float g_nsum[NN*HID];
__device__ float g_z3[NN*MH];
__device__ float g_y4[NN*HID];
__device__ float g_deg[NN];
__device__ float g_statsAll[12*128];  // per (layer,stage): [0..63] sum, [64..127] sumsq
__device__ float g_pool[NG*HID];
__device__ float g_pcnt[NG];

// ------------------- prep -------------------
__global__ void k_prep() {
    int i = blockIdx.x*blockDim.x + threadIdx.x;
    if (i < NN)       g_deg[i]  = 0.f;
    if (i < NG*HID)   g_pool[i] = 0.f;
    if (i < NG)       g_pcnt[i] = 0.f;
    if (i < 12*128)   g_statsAll[i] = 0.f;
}

__global__ void k_deg(const int* __restrict__ ei) {
    int e = blockIdx.x*blockDim.x + threadIdx.x;
    if (e < NE) atomicAdd(&g_deg[ei[NE + e]], 1.0f);
}

// ------------------- input projection: h = x @ Win + b -------------------
__global__ __launch_bounds__(256) void k_init(const float* __restrict__ x,
                                              const float* __restrict__ w,
                                              const float* __restrict__ b) {
    __shared__ float Ws[IND*HID];
    __shared__ float bs[HID];
    __shared__ float xs[4][IND];
    int t = threadIdx.x;
    for (int i = t; i < IND*HID; i += 256) Ws[i] = w[i];
    if (t < HID) bs[t] = b[t];
    int ni = t >> 6, c = t & 63;
    for (int node0 = blockIdx.x*4; node0 < NN; node0 += gridDim.x*4) {
        if (t < 4*IND) xs[t/IND][t%IND] = x[(node0 + t/IND)*IND + (t%IND)];
        __syncthreads();
        int n = node0 + ni;
        float acc = bs[c];
        #pragma unroll
        for (int k = 0; k < IND; k++) acc = fmaf(xs[ni][k], Ws[k*HID + c], acc);
        g_h[n*HID + c] = acc;
        __syncthreads();
    }
}

// ------------------- nodeA: fold residual(BN4), zero nsum, Pa/Pb = h @ [W1a|W1b] -------
// register-tiled 64x64 GEMM, one 64-node tile per block
__global__ __launch_bounds__(256) void k_nodeA(const float* __restrict__ msg_w1,
                                               const float* __restrict__ g2,
                                               const float* __restrict__ be2,
                                               int l) {
    __shared__ float Hs[64][66];
    __shared__ unsigned long long Wp[32][64];   // 16KB
    __shared__ float a4s[64], c4s[64];
    int t = threadIdx.x;
    int fold = (l > 0);
    if (t < 64) {
        float a = 0.f, c = 0.f;
        if (fold) {
            const float* st = g_statsAll + (4*(l-1)+3)*128;
            float mu  = st[t] * (1.0f/NN);
            float var = st[64+t] * (1.0f/NN) - mu*mu;
            a = g2[(l-1)*HID + t] * rsqrtf(var + EPSB);
            c = be2[(l-1)*HID + t] - a*mu;
        }
        a4s[t] = a; c4s[t] = c;
    }
    const float* W = msg_w1 + l*129*MH;
    for (int i = t; i < 32*64; i += 256) {
        int kp = i >> 6, c = i & 63;
        float w0, w1;
        if (c < 32) { w0 = W[(2*kp)*MH + c];          w1 = W[(2*kp+1)*MH + c]; }
        else        { w0 = W[(64+2*kp)*MH + (c-32)];  w1 = W[(64+2*kp+1)*MH + (c-32)]; }
        Wp[kp][c] = pk2(w0, w1);
    }
    __syncthreads();
    int n0 = blockIdx.x * 64;
    {
        int row = t >> 2, cb = (t & 3) * 16;
        int n = n0 + row;
        if (n < NN) {
            float4 z4 = make_float4(0.f,0.f,0.f,0.f);
            #pragma unroll
            for (int u = 0; u < 4; u++) {
                int c = cb + 4*u;
                float4 v = *reinterpret_cast<const float4*>(g_h + n*HID + c);
                if (fold) {
                    float4 y = *reinterpret_cast<const float4*>(g_y4 + n*HID + c);
                    v.x = fmaf(a4s[c+0], y.x, v.x) + c4s[c+0];
                    v.y = fmaf(a4s[c+1], y.y, v.y) + c4s[c+1];
                    v.z = fmaf(a4s[c+2], y.z, v.z) + c4s[c+2];
                    v.w = fmaf(a4s[c+3], y.w, v.w) + c4s[c+3];
                    *reinterpret_cast<float4*>(g_h + n*HID + c) = v;
                }
                *reinterpret_cast<float4*>(g_nsum + n*HID + c) = z4;
                Hs[row][c+0] = v.x; Hs[row][c+1] = v.y;
                Hs[row][c+2] = v.z; Hs[row][c+3] = v.w;
            }
        } else {
            #pragma unroll
            for (int u = 0; u < 16; u++) Hs[row][cb+u] = 0.f;
        }
    }
    __syncthreads();
    int r = t >> 4, q = t & 15;
    unsigned long long acc[4][4];
    #pragma unroll
    for (int n = 0; n < 4; n++)
        #pragma unroll
        for (int c = 0; c < 4; c++) acc[n][c] = 0ULL;
    #pragma unroll 4
    for (int kp = 0; kp < 32; kp++) {
        unsigned long long h2[4];
        #pragma unroll
        for (int n = 0; n < 4; n++)
            h2[n] = *reinterpret_cast<const unsigned long long*>(&Hs[4*r+n][2*kp]);
        ulonglong2 wA = *reinterpret_cast<const ulonglong2*>(&Wp[kp][4*q]);
        ulonglong2 wB = *reinterpret_cast<const ulonglong2*>(&Wp[kp][4*q+2]);
        #pragma unroll
        for (int n = 0; n < 4; n++) {
            acc[n][0] = f2fma(h2[n], wA.x, acc[n][0]);
            acc[n][1] = f2fma(h2[n], wA.y, acc[n][1]);
            acc[n][2] = f2fma(h2[n], wB.x, acc[n][2]);
            acc[n][3] = f2fma(h2[n], wB.y, acc[n][3]);
        }
    }
    #pragma unroll
    for (int n = 0; n < 4; n++) {
        int node = n0 + 4*r + n;
        if (node < NN) {
            float4 o; float lo, hi;
            upk2(acc[n][0], lo, hi); o.x = lo + hi;
            upk2(acc[n][1], lo, hi); o.y = lo + hi;
            upk2(acc[n][2], lo, hi); o.z = lo + hi;
            upk2(acc[n][3], lo, hi); o.w = lo + hi;
            if (q < 8) *reinterpret_cast<float4*>(g_Pa + node*MH + 4*q)        = o;
            else       *reinterpret_cast<float4*>(g_Pb + node*MH + 4*q - 32)   = o;
        }
    }
}

// ------------------- edge stats (R2 smem-transpose version, known-good) -------------
__global__ __launch_bounds__(256) void k_edge_stats(const int* __restrict__ ei,
                                                    const float* __restrict__ eattr,
                                                    const float* __restrict__ msg_w1,
                                                    const float* __restrict__ msg_b1,
                                                    int l) {
    __shared__ float zs[8][32*34];
    __shared__ float wcs[MH], b1s[MH];
    __shared__ float sh[128];
    int t = threadIdx.x, wq = t >> 5, lane = t & 31;
    if (t < MH) { wcs[t] = msg_w1[l*129*MH + 128*MH + t]; b1s[t] = msg_b1[l*MH + t]; }
    if (t < 128) sh[t] = 0.f;
    __syncthreads();
    float sS = 0.f, sQ = 0.f;
    for (int tile = blockIdx.x*8 + wq; tile < NTILE; tile += gridDim.x*8) {
        int e = tile*32 + lane;
        int s = ei[e], d = ei[NE + e];
        float ea = eattr[e];
        const float4* pa = reinterpret_cast<const float4*>(g_Pa + d*MH);
        const float4* pb = reinterpret_cast<const float4*>(g_Pb + s*MH);
        float* zr = &zs[wq][lane*34];
        #pragma unroll
        for (int i = 0; i < 8; i++) {
            float4 A = pa[i], B = pb[i]; int c0 = 4*i;
            zr[c0+0] = A.x + B.x + fmaf(ea, wcs[c0+0], b1s[c0+0]);
            zr[c0+1] = A.y + B.y + fmaf(ea, wcs[c0+1], b1s[c0+1]);
            zr[c0+2] = A.z + B.z + fmaf(ea, wcs[c0+2], b1s[c0+2]);
            zr[c0+3] = A.w + B.w + fmaf(ea, wcs[c0+3], b1s[c0+3]);
        }
        __syncwarp();
        #pragma unroll 8
        for (int e2 = 0; e2 < 32; e2++) {
            float v = zs[wq][e2*34 + lane];   // conflict-free: bank = (2*e2+lane)&31
            sS += v; sQ = fmaf(v, v, sQ);
        }
        __syncwarp();
    }
    atomicAdd(&sh[lane], sS);
    atomicAdd(&sh[64 + lane], sQ);
    __syncthreads();
    if (t < 128) atomicAdd(&g_statsAll[(4*l)*128 + t], sh[t]);
}

// ------------------- edge main: BN1(fold)+ReLU, @W2, ReLU, scatter, stats -------------
__global__ __launch_bounds__(256) void k_edge_main(const int* __restrict__ ei,
                                                   const float* __restrict__ eattr,
                                                   const float* __restrict__ msg_w1,
                                                   const float* __restrict__ msg_b1,
                                                   const float* __restrict__ msg_w2,
                                                   const float* __restrict__ msg_b2,
                                                   const float* __restrict__ g1,
                                                   const float* __restrict__ be1,
                                                   int l) {
    __shared__ float m_s[8][32*34];
    __shared__ int   d_s[8][32];
    __shared__ float a1s[MH], wps[MH], bps[MH];
    __shared__ float sh[128];
    int t = threadIdx.x, wq = t >> 5, lane = t & 31;
    const float* W2 = msg_w2 + l*MH*HID;
    if (t < MH) {
        const float* st = g_statsAll + (4*l)*128;
        float mu  = st[t] * (1.0f/NE);
        float var = st[64+t] * (1.0f/NE) - mu*mu;
        float a1 = g1[l*MH + t] * rsqrtf(var + EPSB);
        float c1 = be1[l*MH + t] - a1*mu;
        a1s[t] = a1;
        wps[t] = a1 * msg_w1[l*129*MH + 128*MH + t];
        bps[t] = fmaf(a1, msg_b1[l*MH + t], c1);
    }
    if (t < 128) sh[t] = 0.f;
    unsigned long long WA[16], WB[16];
    #pragma unroll
    for (int kk = 0; kk < 16; kk++) {
        WA[kk] = pk2(W2[(2*kk)*HID + lane],      W2[(2*kk+1)*HID + lane]);
        WB[kk] = pk2(W2[(2*kk)*HID + lane + 32], W2[(2*kk+1)*HID + lane + 32]);
    }
    float b2a = msg_b2[l*HID + lane], b2b = msg_b2[l*HID + lane + 32];
    __syncthreads();
    float sS0 = 0.f, sQ0 = 0.f, sS1 = 0.f, sQ1 = 0.f;
    for (int tile = blockIdx.x*8 + wq; tile < NTILE; tile += gridDim.x*8) {
        int e = tile*32 + lane;
        int s = ei[e], d = ei[NE + e];
        float ea = eattr[e];
        d_s[wq][lane] = d;
        const float4* pa = reinterpret_cast<const float4*>(g_Pa + d*MH);
        const float4* pb = reinterpret_cast<const float4*>(g_Pb + s*MH);
        float* mr = &m_s[wq][lane*34];
        #pragma unroll
        for (int i = 0; i < 8; i++) {
            float4 A = pa[i], B = pb[i]; int c0 = 4*i;
            mr[c0+0] = fmaxf(fmaf(a1s[c0+0], A.x + B.x, fmaf(ea, wps[c0+0], bps[c0+0])), 0.f);
            mr[c0+1] = fmaxf(fmaf(a1s[c0+1], A.y + B.y, fmaf(ea, wps[c0+1], bps[c0+1])), 0.f);
            mr[c0+2] = fmaxf(fmaf(a1s[c0+2], A.z + B.z, fmaf(ea, wps[c0+2], bps[c0+2])), 0.f);
            mr[c0+3] = fmaxf(fmaf(a1s[c0+3], A.w + B.w, fmaf(ea, wps[c0+3], bps[c0+3])), 0.f);
        }
        __syncwarp();
        #pragma unroll 2
        for (int e2 = 0; e2 < 32; e2++) {
            const unsigned long long* mp =
                reinterpret_cast<const unsigned long long*>(&m_s[wq][e2*34]);
            unsigned long long accA = 0ULL, accB = 0ULL;
            #pragma unroll
            for (int kk = 0; kk < 16; kk++) {
                unsigned long long m2 = mp[kk];
                accA = f2fma(m2, WA[kk], accA);
                accB = f2fma(m2, WB[kk], accB);
            }
            float a0, a1v, b0, b1v;
            upk2(accA, a0, a1v); upk2(accB, b0, b1v);
            float y0 = fmaxf(a0 + a1v + b2a, 0.f);
            float y1 = fmaxf(b0 + b1v + b2b, 0.f);
            sS0 += y0; sQ0 = fmaf(y0, y0, sQ0);
            sS1 += y1; sQ1 = fmaf(y1, y1, sQ1);
            int dd = d_s[wq][e2];
            atomicAdd(&g_nsum[dd*HID + lane],      y0);
            atomicAdd(&g_nsum[dd*HID + lane + 32], y1);
        }
        __syncwarp();
    }
    atomicAdd(&sh[lane],      sS0);
    atomicAdd(&sh[64 + lane], sQ0);
    atomicAdd(&sh[32 + lane], sS1);
    atomicAdd(&sh[96 + lane], sQ1);
    __syncthreads();
    if (t < 128) atomicAdd(&g_statsAll[(4*l+1)*128 + t], sh[t]);
}

// ------------------- update1: z3 = [h, BN2(nsum,deg)] @ U1 + b, stats ---------------
// register-tiled, K split in two halves of 64 (32 k-pairs each)
__global__ __launch_bounds__(256) void k_update1(const float* __restrict__ upd_w1,
                                                 const float* __restrict__ upd_b1,
                                                 const float* __restrict__ g2m,
                                                 const float* __restrict__ be2m,
                                                 int l) {
    __shared__ float Rs[64][66];                 // 16.9KB (one K half)
    __shared__ unsigned long long Wp1[64][32];   // 16KB
    __shared__ float a2s[64], c2s[64];
    __shared__ float sh[128];
    int t = threadIdx.x;
    if (t < 64) {
        const float* st = g_statsAll + (4*l+1)*128;
        float mu  = st[t] * (1.0f/NE);
        float var = st[64+t] * (1.0f/NE) - mu*mu;
        float a = g2m[l*HID + t] * rsqrtf(var + EPSB);
        a2s[t] = a; c2s[t] = be2m[l*HID + t] - a*mu;
    }
    if (t < 128) sh[t] = 0.f;
    const float* U1 = upd_w1 + l*128*MH;
    for (int i = t; i < 64*32; i += 256) {
        int kp = i >> 5, j = i & 31;
        Wp1[kp][j] = pk2(U1[(2*kp)*MH + j], U1[(2*kp+1)*MH + j]);
    }
    int n0 = blockIdx.x * 64;
    int row = t >> 2, cb = (t & 3) * 16;
    int nrow = n0 + row;
    int r = t >> 4, q = t & 15;
    unsigned long long acc[4][2];
    #pragma unroll
    for (int n = 0; n < 4; n++) { acc[n][0] = 0ULL; acc[n][1] = 0ULL; }

    // ---- half 1: k = 0..63 (h part) ----
    __syncthreads();
    if (nrow < NN) {
        #pragma unroll
        for (int u = 0; u < 4; u++) {
            int c = cb + 4*u;
            float4 v = *reinterpret_cast<const float4*>(g_h + nrow*HID + c);
            Rs[row][c+0] = v.x; Rs[row][c+1] = v.y; Rs[row][c+2] = v.z; Rs[row][c+3] = v.w;
        }
    } else {
        #pragma unroll
        for (int u = 0; u < 16; u++) Rs[row][cb+u] = 0.f;
    }
    __syncthreads();
    #pragma unroll 4
    for (int kp = 0; kp < 32; kp++) {
        unsigned long long h2[4];
        #pragma unroll
        for (int n = 0; n < 4; n++)
            h2[n] = *reinterpret_cast<const unsigned long long*>(&Rs[4*r+n][2*kp]);
        ulonglong2 w = *reinterpret_cast<const ulonglong2*>(&Wp1[kp][2*q]);
        #pragma unroll
        for (int n = 0; n < 4; n++) {
            acc[n][0] = f2fma(h2[n], w.x, acc[n][0]);
            acc[n][1] = f2fma(h2[n], w.y, acc[n][1]);
        }
    }
    // ---- half 2: k = 64..127 (agg part) ----
    __syncthreads();
    if (nrow < NN) {
        float dg = g_deg[nrow];
        #pragma unroll
        for (int u = 0; u < 4; u++) {
            int c = cb + 4*u;
            float4 v = *reinterpret_cast<const float4*>(g_nsum + nrow*HID + c);
            v.x = fmaf(a2s[c+0], v.x, c2s[c+0]*dg);
            v.y = fmaf(a2s[c+1], v.y, c2s[c+1]*dg);
            v.z = fmaf(a2s[c+2], v.z, c2s[c+2]*dg);
            v.w = fmaf(a2s[c+3], v.w, c2s[c+3]*dg);
            Rs[row][c+0] = v.x; Rs[row][c+1] = v.y; Rs[row][c+2] = v.z; Rs[row][c+3] = v.w;
        }
    } else {
        #pragma unroll
        for (int u = 0; u < 16; u++) Rs[row][cb+u] = 0.f;
    }
    __syncthreads();
    #pragma unroll 4
    for (int kp = 0; kp < 32; kp++) {
        unsigned long long h2[4];
        #pragma unroll
        for (int n = 0; n < 4; n++)
            h2[n] = *reinterpret_cast<const unsigned long long*>(&Rs[4*r+n][2*kp]);
        ulonglong2 w = *reinterpret_cast<const ulonglong2*>(&Wp1[32+kp][2*q]);
        #pragma unroll
        for (int n = 0; n < 4; n++) {
            acc[n][0] = f2fma(h2[n], w.x, acc[n][0]);
            acc[n][1] = f2fma(h2[n], w.y, acc[n][1]);
        }
    }
    // ---- epilogue ----
    float b30 = upd_b1[l*MH + 2*q], b31 = upd_b1[l*MH + 2*q + 1];
    float s0 = 0.f, q0 = 0.f, s1 = 0.f, q1 = 0.f;
    #pragma unroll
    for (int n = 0; n < 4; n++) {
        int node = n0 + 4*r + n;
        if (node < NN) {
            float lo, hi;
            upk2(acc[n][0], lo, hi); float z0 = lo + hi + b30;
            upk2(acc[n][1], lo, hi); float z1 = lo + hi + b31;
            *reinterpret_cast<float2*>(g_z3 + node*MH + 2*q) = make_float2(z0, z1);
            s0 += z0; q0 = fmaf(z0, z0, q0);
            s1 += z1; q1 = fmaf(z1, z1, q1);
        }
    }
    atomicAdd(&sh[2*q],      s0);
    atomicAdd(&sh[2*q+1],    s1);
    atomicAdd(&sh[64+2*q],   q0);
    atomicAdd(&sh[64+2*q+1], q1);
    __syncthreads();
    if (t < 128) atomicAdd(&g_statsAll[(4*l+2)*128 + t], sh[t]);
}

// ------------------- update2: m3 = relu(BN3(z3)), y4 = relu(m3@U2+b), stats ----------
__global__ __launch_bounds__(256) void k_update2(const float* __restrict__ upd_w2,
                                                 const float* __restrict__ upd_b2,
                                                 const float* __restrict__ g1u,
                                                 const float* __restrict__ be1u,
                                                 int l) {
    __shared__ float m3s[4*MH];
    __shared__ float a3s[MH], c3s[MH];
    __shared__ float sh[128];
    int t = threadIdx.x, ni = t >> 6, c = t & 63;
    const float* U2 = upd_w2 + l*MH*HID;
    unsigned long long Up[16];
    #pragma unroll
    for (int kk = 0; kk < 16; kk++)
        Up[kk] = pk2(U2[(2*kk)*HID + c], U2[(2*kk+1)*HID + c]);
    if (t < MH) {
        const float* st = g_statsAll + (4*l+2)*128;
        float mu  = st[t] * (1.0f/NN);
        float var = st[64+t] * (1.0f/NN) - mu*mu;
        float a = g1u[l*MH + t] * rsqrtf(var + EPSB);
        a3s[t] = a; c3s[t] = be1u[l*MH + t] - a*mu;
    }
    if (t < 128) sh[t] = 0.f;
    float b4 = upd_b2[l*HID + c];
    __syncthreads();
    float accS = 0.f, accQ = 0.f;
    for (int node0 = blockIdx.x*4; node0 < NN; node0 += gridDim.x*4) {
        if (t < 4*MH) {
            int ni2 = t >> 5, k = t & 31;
            float z = g_z3[(node0 + ni2)*MH + k];
            m3s[t] = fmaxf(fmaf(a3s[k], z, c3s[k]), 0.f);
        }
        __syncthreads();
        int n = node0 + ni;
        const unsigned long long* mp =
            reinterpret_cast<const unsigned long long*>(m3s + ni*MH);
        unsigned long long acc = 0ULL;
        #pragma unroll
        for (int kk = 0; kk < 16; kk++) acc = f2fma(mp[kk], Up[kk], acc);
        float lo, hi; upk2(acc, lo, hi);
        float y = fmaxf(lo + hi + b4, 0.f);
        g_y4[n*HID + c] = y;
        accS += y; accQ = fmaf(y, y, accQ);
        __syncthreads();
    }
    atomicAdd(&sh[c], accS);
    atomicAdd(&sh[64 + c], accQ);
    __syncthreads();
    if (t < 128) atomicAdd(&g_statsAll[(4*l+3)*128 + t], sh[t]);
}

// ------------------- pooling (folds last residual, BN4 consts in prologue) ----------
__global__ __launch_bounds__(256) void k_pool(const int* __restrict__ batch,
                                              const float* __restrict__ g2,
                                              const float* __restrict__ be2) {
    __shared__ float a4s[64], c4s[64];
    int t = threadIdx.x;
    if (t < 64) {
        const float* st = g_statsAll + 11*128;
        float mu  = st[t] * (1.0f/NN);
        float var = st[64+t] * (1.0f/NN) - mu*mu;
        float a = g2[2*HID + t] * rsqrtf(var + EPSB);
        a4s[t] = a; c4s[t] = be2[2*HID + t] - a*mu;
    }
    __syncthreads();
    int node0 = blockIdx.x*4;
    int ni = t >> 6, c = t & 63;
    int n = node0 + ni;
    if (n >= NN) return;
    float hn = fmaf(a4s[c], g_y4[n*HID + c], g_h[n*HID + c]) + c4s[c];
    int b = batch[n];
    atomicAdd(&g_pool[b*HID + c], hn);
    if (c == 0) atomicAdd(&g_pcnt[b], 1.0f);
}

__global__ void k_head(const float* __restrict__ out_w, const float* __restrict__ out_b,
                       float* __restrict__ out) {
    int g = blockIdx.x*blockDim.x + threadIdx.x;
    if (g >= NG) return;
    float acc = 0.f;
    #pragma unroll
    for (int k = 0; k < HID; k++) acc = fmaf(g_pool[g*HID + k], __ldg(&out_w[k]), acc);
    float cnt = fmaxf(g_pcnt[g], 1.0f);
    out[g] = fmaxf(acc / cnt + __ldg(&out_b[0]), 0.f);
}

// ------------------- launcher -------------------
extern "C" void kernel_launch(void* const* d_in, const int* in_sizes, int n_in,
                              void* d_out, int out_size) {
    const float* x        = (const float*)d_in[0];
    const int*   ei       = (const int*)  d_in[1];
    const float* eattr    = (const float*)d_in[2];
    const int*   batch    = (const int*)  d_in[3];
    const float* lin_in_w = (const float*)d_in[4];
    const float* lin_in_b = (const float*)d_in[5];
    const float* msg_w1   = (const float*)d_in[6];
    const float* msg_b1   = (const float*)d_in[7];
    const float* msg_g1   = (const float*)d_in[8];
    const float* msg_be1  = (const float*)d_in[9];
    const float* msg_w2   = (const float*)d_in[10];
    const float* msg_b2   = (const float*)d_in[11];
    const float* msg_g2   = (const float*)d_in[12];
    const float* msg_be2  = (const float*)d_in[13];
    const float* upd_w1   = (const float*)d_in[14];
    const float* upd_b1   = (const float*)d_in[15];
    const float* upd_g1   = (const float*)d_in[16];
    const float* upd_be1  = (const float*)d_in[17];
    const float* upd_w2   = (const float*)d_in[18];
    const float* upd_b2   = (const float*)d_in[19];
    const float* upd_g2   = (const float*)d_in[20];
    const float* upd_be2  = (const float*)d_in[21];
    const float* out_w    = (const float*)d_in[22];
    const float* out_b    = (const float*)d_in[23];
    float* out = (float*)d_out;

    k_prep<<<(NN + 255)/256, 256>>>();
    k_deg<<<NE/256, 256>>>(ei);
    k_init<<<GRID_P, 256>>>(x, lin_in_w, lin_in_b);

    for (int l = 0; l < NL; l++) {
        k_nodeA<<<NODE_TILES, 256>>>(msg_w1, upd_g2, upd_be2, l);
        k_edge_stats<<<GRID_P, 256>>>(ei, eattr, msg_w1, msg_b1, l);
        k_edge_main<<<GRID_P, 256>>>(ei, eattr, msg_w1, msg_b1, msg_w2, msg_b2,
                                     msg_g1, msg_be1, l);
        k_update1<<<NODE_TILES, 256>>>(upd_w1, upd_b1, msg_g2, msg_be2, l);
        k_update2<<<GRID_P, 256>>>(upd_w2, upd_b2, upd_g1, upd_be1, l);
    }

    k_pool<<<NN/4, 256>>>(batch, upd_g2, upd_be2);
    k_head<<<2, 256>>>(out_w, out_b, out);
}

// round 9
// speedup vs baseline: 4.2096x; 1.2505x over previous
#include <cuda_runtime.h>

#define NN 100000
#define NE 800000
#define NG 512
#define IND 16
#define HID 64
#define MH  32
#define NL  3
#define EPSB 1e-5f
#define NTILE (NE/32)     // 25000 edge tiles of 32
#define NODE_TILES 1563   // ceil(NN/64)

#define GRID_P 1184       // 8 blocks per SM (148 SMs)

// ------------------- f32x2 packed helpers -------------------
__device__ __forceinline__ unsigned long long pk2(float lo, float hi) {
    unsigned long long r;
    asm("mov.b64 %0,{%1,%2};" : "=l"(r) : "f"(lo), "f"(hi));
    return r;
}
__device__ __forceinline__ void upk2(unsigned long long v, float& lo, float& hi) {
    asm("mov.b64 {%0,%1},%2;" : "=f"(lo), "=f"(hi) : "l"(v));
}
__device__ __forceinline__ unsigned long long f2fma(unsigned long long a,
                                                    unsigned long long b,
                                                    unsigned long long c) {
    unsigned long long r;
    asm("fma.rn.f32x2 %0,%1,%2,%3;" : "=l"(r) : "l"(a), "l"(b), "l"(c));
    return r;
}

// ------------------- scratch (static device memory; no allocs) -------------------
__device__ float g_h[NN*HID];
__device__ float g_Pa[NN*MH];
__device__ float g_Pb[NN*MH];
__device__ float g_nsum[NN*HID];
__device__ float g_z3[NN*MH];
__device__ float g_y4[NN*HID];
__device__ float g_deg[NN];
__device__ float g_statsAll[12*128];  // per (layer,stage): [0..63] sum, [64..127] sumsq
__device__ float g_pool[NG*HID];
__device__ float g_pcnt[NG];

// ------------------- prep -------------------
__global__ void k_prep() {
    int i = blockIdx.x*blockDim.x + threadIdx.x;
    if (i < NN)       g_deg[i]  = 0.f;
    if (i < NG*HID)   g_pool[i] = 0.f;
    if (i < NG)       g_pcnt[i] = 0.f;
    if (i < 12*128)   g_statsAll[i] = 0.f;
}

__global__ void k_deg(const int* __restrict__ ei) {
    int e = blockIdx.x*blockDim.x + threadIdx.x;
    if (e < NE) atomicAdd(&g_deg[ei[NE + e]], 1.0f);
}

// ------------------- input projection: h = x @ Win + b (barrier-free loop) ---------
__global__ __launch_bounds__(256) void k_init(const float* __restrict__ x,
                                              const float* __restrict__ w,
                                              const float* __restrict__ b) {
    __shared__ float Ws[IND*HID];
    int t = threadIdx.x;
    for (int i = t; i < IND*HID; i += 256) Ws[i] = w[i];
    int ni = t >> 6, c = t & 63;
    float bc = __ldg(&b[c]);
    __syncthreads();
    for (int node0 = blockIdx.x*4; node0 < NN; node0 += gridDim.x*4) {
        int n = node0 + ni;
        const float* xr = x + n*IND;
        float acc = bc;
        #pragma unroll
        for (int k = 0; k < IND; k++) acc = fmaf(__ldg(xr + k), Ws[k*HID + c], acc);
        g_h[n*HID + c] = acc;
    }
}

// ------------------- nodeA: fold residual(BN4), zero nsum, Pa/Pb = h @ [W1a|W1b] -------
// register-tiled 64x64 GEMM, one 64-node tile per block  (unchanged from R8)
__global__ __launch_bounds__(256) void k_nodeA(const float* __restrict__ msg_w1,
                                               const float* __restrict__ g2,
                                               const float* __restrict__ be2,
                                               int l) {
    __shared__ float Hs[64][66];
    __shared__ unsigned long long Wp[32][64];   // 16KB
    __shared__ float a4s[64], c4s[64];
    int t = threadIdx.x;
    int fold = (l > 0);
    if (t < 64) {
        float a = 0.f, c = 0.f;
        if (fold) {
            const float* st = g_statsAll + (4*(l-1)+3)*128;
            float mu  = st[t] * (1.0f/NN);
            float var = st[64+t] * (1.0f/NN) - mu*mu;
            a = g2[(l-1)*HID + t] * rsqrtf(var + EPSB);
            c = be2[(l-1)*HID + t] - a*mu;
        }
        a4s[t] = a; c4s[t] = c;
    }
    const float* W = msg_w1 + l*129*MH;
    for (int i = t; i < 32*64; i += 256) {
        int kp = i >> 6, c = i & 63;
        float w0, w1;
        if (c < 32) { w0 = W[(2*kp)*MH + c];          w1 = W[(2*kp+1)*MH + c]; }
        else        { w0 = W[(64+2*kp)*MH + (c-32)];  w1 = W[(64+2*kp+1)*MH + (c-32)]; }
        Wp[kp][c] = pk2(w0, w1);
    }
    __syncthreads();
    int n0 = blockIdx.x * 64;
    {
        int row = t >> 2, cb = (t & 3) * 16;
        int n = n0 + row;
        if (n < NN) {
            float4 z4 = make_float4(0.f,0.f,0.f,0.f);
            #pragma unroll
            for (int u = 0; u < 4; u++) {
                int c = cb + 4*u;
                float4 v = *reinterpret_cast<const float4*>(g_h + n*HID + c);
                if (fold) {
                    float4 y = *reinterpret_cast<const float4*>(g_y4 + n*HID + c);
                    v.x = fmaf(a4s[c+0], y.x, v.x) + c4s[c+0];
                    v.y = fmaf(a4s[c+1], y.y, v.y) + c4s[c+1];
                    v.z = fmaf(a4s[c+2], y.z, v.z) + c4s[c+2];
                    v.w = fmaf(a4s[c+3], y.w, v.w) + c4s[c+3];
                    *reinterpret_cast<float4*>(g_h + n*HID + c) = v;
                }
                *reinterpret_cast<float4*>(g_nsum + n*HID + c) = z4;
                Hs[row][c+0] = v.x; Hs[row][c+1] = v.y;
                Hs[row][c+2] = v.z; Hs[row][c+3] = v.w;
            }
        } else {
            #pragma unroll
            for (int u = 0; u < 16; u++) Hs[row][cb+u] = 0.f;
        }
    }
    __syncthreads();
    int r = t >> 4, q = t & 15;
    unsigned long long acc[4][4];
    #pragma unroll
    for (int n = 0; n < 4; n++)
        #pragma unroll
        for (int c = 0; c < 4; c++) acc[n][c] = 0ULL;
    #pragma unroll 4
    for (int kp = 0; kp < 32; kp++) {
        unsigned long long h2[4];
        #pragma unroll
        for (int n = 0; n < 4; n++)
            h2[n] = *reinterpret_cast<const unsigned long long*>(&Hs[4*r+n][2*kp]);
        ulonglong2 wA = *reinterpret_cast<const ulonglong2*>(&Wp[kp][4*q]);
        ulonglong2 wB = *reinterpret_cast<const ulonglong2*>(&Wp[kp][4*q+2]);
        #pragma unroll
        for (int n = 0; n < 4; n++) {
            acc[n][0] = f2fma(h2[n], wA.x, acc[n][0]);
            acc[n][1] = f2fma(h2[n], wA.y, acc[n][1]);
            acc[n][2] = f2fma(h2[n], wB.x, acc[n][2]);
            acc[n][3] = f2fma(h2[n], wB.y, acc[n][3]);
        }
    }
    #pragma unroll
    for (int n = 0; n < 4; n++) {
        int node = n0 + 4*r + n;
        if (node < NN) {
            float4 o; float lo, hi;
            upk2(acc[n][0], lo, hi); o.x = lo + hi;
            upk2(acc[n][1], lo, hi); o.y = lo + hi;
            upk2(acc[n][2], lo, hi); o.z = lo + hi;
            upk2(acc[n][3], lo, hi); o.w = lo + hi;
            if (q < 8) *reinterpret_cast<float4*>(g_Pa + node*MH + 4*q)        = o;
            else       *reinterpret_cast<float4*>(g_Pb + node*MH + 4*q - 32)   = o;
        }
    }
}

// ------------------- edge stats (lane = channel, coalesced gathers) -----------------
__global__ __launch_bounds__(256) void k_edge_stats(const int* __restrict__ ei,
                                                    const float* __restrict__ eattr,
                                                    const float* __restrict__ msg_w1,
                                                    const float* __restrict__ msg_b1,
                                                    int l) {
    __shared__ int   ss[8][32], ds[8][32];
    __shared__ float eas[8][32];
    __shared__ float sh[128];
    int t = threadIdx.x, wq = t >> 5, lane = t & 31;
    float wcr = __ldg(&msg_w1[l*129*MH + 128*MH + lane]);
    float b1r = __ldg(&msg_b1[l*MH + lane]);
    if (t < 128) sh[t] = 0.f;
    __syncthreads();
    float sS = 0.f, sQ = 0.f;
    for (int tile = blockIdx.x*8 + wq; tile < NTILE; tile += gridDim.x*8) {
        int e = tile*32 + lane;
        ss[wq][lane]  = ei[e];
        ds[wq][lane]  = ei[NE + e];
        eas[wq][lane] = eattr[e];
        __syncwarp();
        #pragma unroll 4
        for (int e2 = 0; e2 < 32; e2++) {
            int s = ss[wq][e2], d = ds[wq][e2];
            float ea = eas[wq][e2];
            float pa = g_Pa[d*MH + lane];   // coalesced: 1 wavefront
            float pb = g_Pb[s*MH + lane];
            float z = pa + pb + fmaf(ea, wcr, b1r);
            sS += z; sQ = fmaf(z, z, sQ);
        }
        __syncwarp();
    }
    atomicAdd(&sh[lane], sS);
    atomicAdd(&sh[64 + lane], sQ);
    __syncthreads();
    if (t < 128) atomicAdd(&g_statsAll[(4*l)*128 + t], sh[t]);
}

// ------------------- edge main: coalesced phase A, GEMM phase B ---------------------
__global__ __launch_bounds__(256) void k_edge_main(const int* __restrict__ ei,
                                                   const float* __restrict__ eattr,
                                                   const float* __restrict__ msg_w1,
                                                   const float* __restrict__ msg_b1,
                                                   const float* __restrict__ msg_w2,
                                                   const float* __restrict__ msg_b2,
                                                   const float* __restrict__ g1,
                                                   const float* __restrict__ be1,
                                                   int l) {
    __shared__ float m_s[8][32*34];
    __shared__ int   ss[8][32], ds[8][32];
    __shared__ float eas[8][32];
    __shared__ float a1s[MH], wps[MH], bps[MH];
    __shared__ float sh[128];
    int t = threadIdx.x, wq = t >> 5, lane = t & 31;
    const float* W2 = msg_w2 + l*MH*HID;
    if (t < MH) {
        const float* st = g_statsAll + (4*l)*128;
        float mu  = st[t] * (1.0f/NE);
        float var = st[64+t] * (1.0f/NE) - mu*mu;
        float a1 = g1[l*MH + t] * rsqrtf(var + EPSB);
        float c1 = be1[l*MH + t] - a1*mu;
        a1s[t] = a1;
        wps[t] = a1 * msg_w1[l*129*MH + 128*MH + t];
        bps[t] = fmaf(a1, msg_b1[l*MH + t], c1);
    }
    if (t < 128) sh[t] = 0.f;
    unsigned long long WA[16], WB[16];
    #pragma unroll
    for (int kk = 0; kk < 16; kk++) {
        WA[kk] = pk2(W2[(2*kk)*HID + lane],      W2[(2*kk+1)*HID + lane]);
        WB[kk] = pk2(W2[(2*kk)*HID + lane + 32], W2[(2*kk+1)*HID + lane + 32]);
    }
    float b2a = msg_b2[l*HID + lane], b2b = msg_b2[l*HID + lane + 32];
    __syncthreads();
    float a1r = a1s[lane], wpr = wps[lane], bpr = bps[lane];   // lane = channel
    float sS0 = 0.f, sQ0 = 0.f, sS1 = 0.f, sQ1 = 0.f;
    for (int tile = blockIdx.x*8 + wq; tile < NTILE; tile += gridDim.x*8) {
        int e = tile*32 + lane;
        ss[wq][lane]  = ei[e];
        ds[wq][lane]  = ei[NE + e];
        eas[wq][lane] = eattr[e];
        __syncwarp();
        // ---- phase A: lane = channel, edges sequential; coalesced gathers ----
        #pragma unroll 4
        for (int e2 = 0; e2 < 32; e2++) {
            int s = ss[wq][e2], d = ds[wq][e2];
            float ea = eas[wq][e2];
            float pa = g_Pa[d*MH + lane];   // 1 wavefront
            float pb = g_Pb[s*MH + lane];
            m_s[wq][e2*34 + lane] =
                fmaxf(fmaf(a1r, pa + pb, fmaf(ea, wpr, bpr)), 0.f);
        }
        __syncwarp();
        // ---- phase B: lane = output channel pair (lane, lane+32) ----
        #pragma unroll 2
        for (int e2 = 0; e2 < 32; e2++) {
            const unsigned long long* mp =
                reinterpret_cast<const unsigned long long*>(&m_s[wq][e2*34]);
            unsigned long long accA = 0ULL, accB = 0ULL;
            #pragma unroll
            for (int kk = 0; kk < 16; kk++) {
                unsigned long long m2 = mp[kk];
                accA = f2fma(m2, WA[kk], accA);
                accB = f2fma(m2, WB[kk], accB);
            }
            float a0, a1v, b0, b1v;
            upk2(accA, a0, a1v); upk2(accB, b0, b1v);
            float y0 = fmaxf(a0 + a1v + b2a, 0.f);
            float y1 = fmaxf(b0 + b1v + b2b, 0.f);
            sS0 += y0; sQ0 = fmaf(y0, y0, sQ0);
            sS1 += y1; sQ1 = fmaf(y1, y1, sQ1);
            int dd = ds[wq][e2];
            atomicAdd(&g_nsum[dd*HID + lane],      y0);
            atomicAdd(&g_nsum[dd*HID + lane + 32], y1);
        }
        __syncwarp();
    }
    atomicAdd(&sh[lane],      sS0);
    atomicAdd(&sh[64 + lane], sQ0);
    atomicAdd(&sh[32 + lane], sS1);
    atomicAdd(&sh[96 + lane], sQ1);
    __syncthreads();
    if (t < 128) atomicAdd(&g_statsAll[(4*l+1)*128 + t], sh[t]);
}

// ------------------- update1: z3 = [h, BN2(nsum,deg)] @ U1 + b, stats ---------------
// register-tiled, K split in two halves of 64 (32 k-pairs each)  (unchanged from R8)
__global__ __launch_bounds__(256) void k_update1(const float* __restrict__ upd_w1,
                                                 const float* __restrict__ upd_b1,
                                                 const float* __restrict__ g2m,
                                                 const float* __restrict__ be2m,
                                                 int l) {
    __shared__ float Rs[64][66];                 // 16.9KB (one K half)
    __shared__ unsigned long long Wp1[64][32];   // 16KB
    __shared__ float a2s[64], c2s[64];
    __shared__ float sh[128];
    int t = threadIdx.x;
    if (t < 64) {
        const float* st = g_statsAll + (4*l+1)*128;
        float mu  = st[t] * (1.0f/NE);
        float var = st[64+t] * (1.0f/NE) - mu*mu;
        float a = g2m[l*HID + t] * rsqrtf(var + EPSB);
        a2s[t] = a; c2s[t] = be2m[l*HID + t] - a*mu;
    }
    if (t < 128) sh[t] = 0.f;
    const float* U1 = upd_w1 + l*128*MH;
    for (int i = t; i < 64*32; i += 256) {
        int kp = i >> 5, j = i & 31;
        Wp1[kp][j] = pk2(U1[(2*kp)*MH + j], U1[(2*kp+1)*MH + j]);
    }
    int n0 = blockIdx.x * 64;
    int row = t >> 2, cb = (t & 3) * 16;
    int nrow = n0 + row;
    int r = t >> 4, q = t & 15;
    unsigned long long acc[4][2];
    #pragma unroll
    for (int n = 0; n < 4; n++) { acc[n][0] = 0ULL; acc[n][1] = 0ULL; }

    // ---- half 1: k = 0..63 (h part) ----
    __syncthreads();
    if (nrow < NN) {
        #pragma unroll
        for (int u = 0; u < 4; u++) {
            int c = cb + 4*u;
            float4 v = *reinterpret_cast<const float4*>(g_h + nrow*HID + c);
            Rs[row][c+0] = v.x; Rs[row][c+1] = v.y; Rs[row][c+2] = v.z; Rs[row][c+3] = v.w;
        }
    } else {
        #pragma unroll
        for (int u = 0; u < 16; u++) Rs[row][cb+u] = 0.f;
    }
    __syncthreads();
    #pragma unroll 4
    for (int kp = 0; kp < 32; kp++) {
        unsigned long long h2[4];
        #pragma unroll
        for (int n = 0; n < 4; n++)
            h2[n] = *reinterpret_cast<const unsigned long long*>(&Rs[4*r+n][2*kp]);
        ulonglong2 w = *reinterpret_cast<const ulonglong2*>(&Wp1[kp][2*q]);
        #pragma unroll
        for (int n = 0; n < 4; n++) {
            acc[n][0] = f2fma(h2[n], w.x, acc[n][0]);
            acc[n][1] = f2fma(h2[n], w.y, acc[n][1]);
        }
    }
    // ---- half 2: k = 64..127 (agg part) ----
    __syncthreads();
    if (nrow < NN) {
        float dg = g_deg[nrow];
        #pragma unroll
        for (int u = 0; u < 4; u++) {
            int c = cb + 4*u;
            float4 v = *reinterpret_cast<const float4*>(g_nsum + nrow*HID + c);
            v.x = fmaf(a2s[c+0], v.x, c2s[c+0]*dg);
            v.y = fmaf(a2s[c+1], v.y, c2s[c+1]*dg);
            v.z = fmaf(a2s[c+2], v.z, c2s[c+2]*dg);
            v.w = fmaf(a2s[c+3], v.w, c2s[c+3]*dg);
            Rs[row][c+0] = v.x; Rs[row][c+1] = v.y; Rs[row][c+2] = v.z; Rs[row][c+3] = v.w;
        }
    } else {
        #pragma unroll
        for (int u = 0; u < 16; u++) Rs[row][cb+u] = 0.f;
    }
    __syncthreads();
    #pragma unroll 4
    for (int kp = 0; kp < 32; kp++) {
        unsigned long long h2[4];
        #pragma unroll
        for (int n = 0; n < 4; n++)
            h2[n] = *reinterpret_cast<const unsigned long long*>(&Rs[4*r+n][2*kp]);
        ulonglong2 w = *reinterpret_cast<const ulonglong2*>(&Wp1[32+kp][2*q]);
        #pragma unroll
        for (int n = 0; n < 4; n++) {
            acc[n][0] = f2fma(h2[n], w.x, acc[n][0]);
            acc[n][1] = f2fma(h2[n], w.y, acc[n][1]);
        }
    }
    // ---- epilogue ----
    float b30 = upd_b1[l*MH + 2*q], b31 = upd_b1[l*MH + 2*q + 1];
    float s0 = 0.f, q0 = 0.f, s1 = 0.f, q1 = 0.f;
    #pragma unroll
    for (int n = 0; n < 4; n++) {
        int node = n0 + 4*r + n;
        if (node < NN) {
            float lo, hi;
            upk2(acc[n][0], lo, hi); float z0 = lo + hi + b30;
            upk2(acc[n][1], lo, hi); float z1 = lo + hi + b31;
            *reinterpret_cast<float2*>(g_z3 + node*MH + 2*q) = make_float2(z0, z1);
            s0 += z0; q0 = fmaf(z0, z0, q0);
            s1 += z1; q1 = fmaf(z1, z1, q1);
        }
    }
    atomicAdd(&sh[2*q],      s0);
    atomicAdd(&sh[2*q+1],    s1);
    atomicAdd(&sh[64+2*q],   q0);
    atomicAdd(&sh[64+2*q+1], q1);
    __syncthreads();
    if (t < 128) atomicAdd(&g_statsAll[(4*l+2)*128 + t], sh[t]);
}

// ------------------- update2: m3 = relu(BN3(z3)), y4 = relu(m3@U2+b), stats ----------
__global__ __launch_bounds__(256) void k_update2(const float* __restrict__ upd_w2,
                                                 const float* __restrict__ upd_b2,
                                                 const float* __restrict__ g1u,
                                                 const float* __restrict__ be1u,
                                                 int l) {
    __shared__ float m3s[4*MH];
    __shared__ float a3s[MH], c3s[MH];
    __shared__ float sh[128];
    int t = threadIdx.x, ni = t >> 6, c = t & 63;
    const float* U2 = upd_w2 + l*MH*HID;
    unsigned long long Up[16];
    #pragma unroll
    for (int kk = 0; kk < 16; kk++)
        Up[kk] = pk2(U2[(2*kk)*HID + c], U2[(2*kk+1)*HID + c]);
    if (t < MH) {
        const float* st = g_statsAll + (4*l+2)*128;
        float mu  = st[t] * (1.0f/NN);
        float var = st[64+t] * (1.0f/NN) - mu*mu;
        float a = g1u[l*MH + t] * rsqrtf(var + EPSB);
        a3s[t] = a; c3s[t] = be1u[l*MH + t] - a*mu;
    }
    if (t < 128) sh[t] = 0.f;
    float b4 = upd_b2[l*HID + c];
    __syncthreads();
    float accS = 0.f, accQ = 0.f;
    for (int node0 = blockIdx.x*4; node0 < NN; node0 += gridDim.x*4) {
        if (t < 4*MH) {
            int ni2 = t >> 5, k = t & 31;
            float z = g_z3[(node0 + ni2)*MH + k];
            m3s[t] = fmaxf(fmaf(a3s[k], z, c3s[k]), 0.f);
        }
        __syncthreads();
        int n = node0 + ni;
        const unsigned long long* mp =
            reinterpret_cast<const unsigned long long*>(m3s + ni*MH);
        unsigned long long acc = 0ULL;
        #pragma unroll
        for (int kk = 0; kk < 16; kk++) acc = f2fma(mp[kk], Up[kk], acc);
        float lo, hi; upk2(acc, lo, hi);
        float y = fmaxf(lo + hi + b4, 0.f);
        g_y4[n*HID + c] = y;
        accS += y; accQ = fmaf(y, y, accQ);
        __syncthreads();
    }
    atomicAdd(&sh[c], accS);
    atomicAdd(&sh[64 + c], accQ);
    __syncthreads();
    if (t < 128) atomicAdd(&g_statsAll[(4*l+3)*128 + t], sh[t]);
}

// ------------------- pooling (folds last residual, BN4 consts in prologue) ----------
__global__ __launch_bounds__(256) void k_pool(const int* __restrict__ batch,
                                              const float* __restrict__ g2,
                                              const float* __restrict__ be2) {
    __shared__ float a4s[64], c4s[64];
    int t = threadIdx.x;
    if (t < 64) {
        const float* st = g_statsAll + 11*128;
        float mu  = st[t] * (1.0f/NN);
        float var = st[64+t] * (1.0f/NN) - mu*mu;
        float a = g2[2*HID + t] * rsqrtf(var + EPSB);
        a4s[t] = a; c4s[t] = be2[2*HID + t] - a*mu;
    }
    __syncthreads();
    int node0 = blockIdx.x*4;
    int ni = t >> 6, c = t & 63;
    int n = node0 + ni;
    if (n >= NN) return;
    float hn = fmaf(a4s[c], g_y4[n*HID + c], g_h[n*HID + c]) + c4s[c];
    int b = batch[n];
    atomicAdd(&g_pool[b*HID + c], hn);
    if (c == 0) atomicAdd(&g_pcnt[b], 1.0f);
}

__global__ void k_head(const float* __restrict__ out_w, const float* __restrict__ out_b,
                       float* __restrict__ out) {
    int g = blockIdx.x*blockDim.x + threadIdx.x;
    if (g >= NG) return;
    float acc = 0.f;
    #pragma unroll
    for (int k = 0; k < HID; k++) acc = fmaf(g_pool[g*HID + k], __ldg(&out_w[k]), acc);
    float cnt = fmaxf(g_pcnt[g], 1.0f);
    out[g] = fmaxf(acc / cnt + __ldg(&out_b[0]), 0.f);
}

// ------------------- launcher -------------------
extern "C" void kernel_launch(void* const* d_in, const int* in_sizes, int n_in,
                              void* d_out, int out_size) {
    const float* x        = (const float*)d_in[0];
    const int*   ei       = (const int*)  d_in[1];
    const float* eattr    = (const float*)d_in[2];
    const int*   batch    = (const int*)  d_in[3];
    const float* lin_in_w = (const float*)d_in[4];
    const float* lin_in_b = (const float*)d_in[5];
    const float* msg_w1   = (const float*)d_in[6];
    const float* msg_b1   = (const float*)d_in[7];
    const float* msg_g1   = (const float*)d_in[8];
    const float* msg_be1  = (const float*)d_in[9];
    const float* msg_w2   = (const float*)d_in[10];
    const float* msg_b2   = (const float*)d_in[11];
    const float* msg_g2   = (const float*)d_in[12];
    const float* msg_be2  = (const float*)d_in[13];
    const float* upd_w1   = (const float*)d_in[14];
    const float* upd_b1   = (const float*)d_in[15];
    const float* upd_g1   = (const float*)d_in[16];
    const float* upd_be1  = (const float*)d_in[17];
    const float* upd_w2   = (const float*)d_in[18];
    const float* upd_b2   = (const float*)d_in[19];
    const float* upd_g2   = (const float*)d_in[20];
    const float* upd_be2  = (const float*)d_in[21];
    const float* out_w    = (const float*)d_in[22];
    const float* out_b    = (const float*)d_in[23];
    float* out = (float*)d_out;

    k_prep<<<(NN + 255)/256, 256>>>();
    k_deg<<<NE/256, 256>>>(ei);
    k_init<<<GRID_P, 256>>>(x, lin_in_w, lin_in_b);

    for (int l = 0; l < NL; l++) {
        k_nodeA<<<NODE_TILES, 256>>>(msg_w1, upd_g2, upd_be2, l);
        k_edge_stats<<<GRID_P, 256>>>(ei, eattr, msg_w1, msg_b1, l);
        k_edge_main<<<GRID_P, 256>>>(ei, eattr, msg_w1, msg_b1, msg_w2, msg_b2,
                                     msg_g1, msg_be1, l);
        k_update1<<<NODE_TILES, 256>>>(upd_w1, upd_b1, msg_g2, msg_be2, l);
        k_update2<<<GRID_P, 256>>>(upd_w2, upd_b2, upd_g1, upd_be1, l);
    }

    k_pool<<<NN/4, 256>>>(batch, upd_g2, upd_be2);
    k_head<<<2, 256>>>(out_w, out_b, out);
}